// round 2
// baseline (speedup 1.0000x reference)
#include <cuda_runtime.h>
#include <cuda_bf16.h>
#include <cstdint>

// Problem shape (fixed by dataset: X is [8192, 64] fp32)
#define NROWS 8192
#define DDIM  64

// -------- device scratch (static allocation only) ---------------------------
__device__ float g_sq[NROWS];        // per-row ||x||^2 (fp32, exact)
__device__ float g_cp[64 * DDIM];    // partial column sums (64 blocks x 64 cols)
__device__ float g_invl;             // log2(e) / (2*sigma^2)

// ------------------------- kernel 1: per-row ||x||^2 ------------------------
__global__ void gk_sq(const float* __restrict__ X) {
    int gtid = blockIdx.x * blockDim.x + threadIdx.x;
    int w = gtid >> 5;                 // one warp per row
    int lane = threadIdx.x & 31;
    const float* row = X + (size_t)w * DDIM;
    float a = row[lane], b = row[lane + 32];
    float p = a * a + b * b;
    #pragma unroll
    for (int o = 16; o > 0; o >>= 1)
        p += __shfl_xor_sync(0xffffffffu, p, o);
    if (lane == 0) g_sq[w] = p;
}

// --------------- kernel 2: partial column sums (for mean vector) ------------
// 64 blocks x 1024 threads; block handles 128 rows. col = t&63, stripe = t>>6.
__global__ void gk_colpart(const float* __restrict__ X) {
    __shared__ float scs[1024];
    int t = threadIdx.x;
    int col = t & 63, stripe = t >> 6;         // 16 stripes x 8 rows
    int base = blockIdx.x * 128 + stripe * 8;
    float s = 0.f;
    #pragma unroll
    for (int r = 0; r < 8; r++)
        s += X[(size_t)(base + r) * DDIM + col];
    scs[t] = s;
    __syncthreads();
    if (t < 64) {
        float c = 0.f;
        #pragma unroll
        for (int st = 0; st < 16; st++) c += scs[st * 64 + t];
        g_cp[blockIdx.x * 64 + t] = c;
    }
}

// --------------- kernel 3: finish stats -> log2e/(2 sigma^2) ----------------
// mean(d2) = 2*mean(sq) - 2*||mu||^2 (clamp correction is O(1e-9) relative)
__global__ void gk_finish(int n) {
    __shared__ float ssq[1024];
    __shared__ float smu[64];
    int t = threadIdx.x;
    float q = 0.f;
    for (int r = t; r < n; r += 1024) q += g_sq[r];
    ssq[t] = q;
    __syncthreads();
    for (int sft = 512; sft > 0; sft >>= 1) {
        if (t < sft) ssq[t] += ssq[t + sft];
        __syncthreads();
    }
    if (t < 64) {
        float c = 0.f;
        #pragma unroll
        for (int b = 0; b < 64; b++) c += g_cp[b * 64 + t];
        smu[t] = c / (float)n;                 // mu_k
    }
    __syncthreads();
    if (t == 0) {
        float mu2 = 0.f;
        #pragma unroll
        for (int k = 0; k < 64; k++) mu2 += smu[k] * smu[k];
        float meansq = ssq[0] / (float)n;
        float meand2 = 2.f * meansq - 2.f * mu2;   // ALPHA = 1
        g_invl = 1.44269504f / (2.f * meand2);     // log2(e)/(2 sigma^2)
    }
}

// ------------------------- kernel 4: main tile kernel ------------------------
// CTA: 128x128 output tile via tf32 mma.sync.m16n8k8, register accumulators.
// 8 warps laid out 4(m) x 2(n); warp tile 32x64.
#define BM 128
#define BN 128
#define SA_STRIDE 68   // floats; 68%32=4 -> conflict-free fragment LDS

static constexpr int SMEM_FLOATS = 2 * BM * SA_STRIDE + 256;
static constexpr int SMEM_BYTES  = SMEM_FLOATS * 4;   // 70656

__device__ __forceinline__ uint32_t f2tf32(float x) {
    uint32_t r;
    asm("cvt.rna.tf32.f32 %0, %1;" : "=r"(r) : "f"(x));
    return r;
}

__device__ __forceinline__ void mma_tf32(float* c, const uint32_t* a, const uint32_t* b) {
    asm volatile(
        "mma.sync.aligned.m16n8k8.row.col.f32.tf32.tf32.f32 "
        "{%0,%1,%2,%3}, {%4,%5,%6,%7}, {%8,%9}, {%0,%1,%2,%3};"
        : "+f"(c[0]), "+f"(c[1]), "+f"(c[2]), "+f"(c[3])
        : "r"(a[0]), "r"(a[1]), "r"(a[2]), "r"(a[3]), "r"(b[0]), "r"(b[1]));
}

__device__ __forceinline__ float gauss_elem(float acc, float sj, float nsqi, float invl) {
    float u = fmaf(2.f, acc, nsqi - sj);   // u = 2*dot - sq_i - sq_j = -d2
    float a = fminf(u * invl, 0.f);        // = -max(d2,0)*log2e/(2 sigma^2)
    float r;
    asm("ex2.approx.f32 %0, %1;" : "=f"(r) : "f"(a));
    return r;
}

__global__ void __launch_bounds__(256, 2)
gk_main(const float* __restrict__ X, float* __restrict__ out, int n) {
    extern __shared__ float smem[];
    float* As  = smem;                          // [128][68] tf32 bits
    float* Bs  = smem + BM * SA_STRIDE;         // [128][68]
    float* sqi = smem + 2 * BM * SA_STRIDE;     // [128]
    float* sqj = sqi + 128;                     // [128]

    int tid = threadIdx.x;
    int bi = blockIdx.y, bj = blockIdx.x;

    // ---- cooperative load: global fp32 -> tf32-rounded bits in SMEM --------
    {
        const float4* gA = reinterpret_cast<const float4*>(X + (size_t)bi * BM * DDIM);
        const float4* gB = reinterpret_cast<const float4*>(X + (size_t)bj * BN * DDIM);
        #pragma unroll
        for (int c = 0; c < 8; c++) {
            int e = tid + 256 * c;              // 2048 float4 per tile
            int row = e >> 4, q = e & 15;
            float4 va = gA[e];
            float4 vb = gB[e];
            uint32_t* da = reinterpret_cast<uint32_t*>(&As[row * SA_STRIDE + q * 4]);
            uint32_t* db = reinterpret_cast<uint32_t*>(&Bs[row * SA_STRIDE + q * 4]);
            da[0] = f2tf32(va.x); da[1] = f2tf32(va.y);
            da[2] = f2tf32(va.z); da[3] = f2tf32(va.w);
            db[0] = f2tf32(vb.x); db[1] = f2tf32(vb.y);
            db[2] = f2tf32(vb.z); db[3] = f2tf32(vb.w);
        }
        if (tid < 128) sqi[tid] = g_sq[bi * BM + tid];
        else           sqj[tid - 128] = g_sq[bj * BN + (tid - 128)];
    }
    __syncthreads();

    // ---- warp-level tf32 GEMM ----------------------------------------------
    int wid = tid >> 5, lane = tid & 31;
    int wm = wid & 3, wn = wid >> 2;            // 4 x 2 warp grid
    int gq = lane >> 2, q4 = lane & 3;          // group / quad-thread

    float acc[2][8][4];
    #pragma unroll
    for (int mt = 0; mt < 2; mt++)
        #pragma unroll
        for (int nt = 0; nt < 8; nt++)
            #pragma unroll
            for (int r = 0; r < 4; r++) acc[mt][nt][r] = 0.f;

    const uint32_t* Au = reinterpret_cast<const uint32_t*>(As);
    const uint32_t* Bu = reinterpret_cast<const uint32_t*>(Bs);

    #pragma unroll
    for (int kk = 0; kk < 8; kk++) {
        int k0 = kk * 8 + q4;
        uint32_t afr[2][4];
        #pragma unroll
        for (int mt = 0; mt < 2; mt++) {
            int row = wm * 32 + mt * 16 + gq;
            afr[mt][0] = Au[row * SA_STRIDE + k0];
            afr[mt][1] = Au[(row + 8) * SA_STRIDE + k0];
            afr[mt][2] = Au[row * SA_STRIDE + k0 + 4];
            afr[mt][3] = Au[(row + 8) * SA_STRIDE + k0 + 4];
        }
        uint32_t bfr[8][2];
        #pragma unroll
        for (int nt = 0; nt < 8; nt++) {
            int col = wn * 64 + nt * 8 + gq;
            bfr[nt][0] = Bu[col * SA_STRIDE + k0];
            bfr[nt][1] = Bu[col * SA_STRIDE + k0 + 4];
        }
        #pragma unroll
        for (int mt = 0; mt < 2; mt++)
            #pragma unroll
            for (int nt = 0; nt < 8; nt++)
                mma_tf32(acc[mt][nt], afr[mt], bfr[nt]);
    }

    // ---- fused epilogue: exp(-max(d2,0)/(2 sigma^2)), direct STG -----------
    float invl = g_invl;
    #pragma unroll
    for (int mt = 0; mt < 2; mt++) {
        #pragma unroll
        for (int rr = 0; rr < 2; rr++) {
            int rloc = wm * 32 + mt * 16 + gq + rr * 8;
            int grow = bi * BM + rloc;
            float nsqi = -sqi[rloc];
            float* orow = out + (size_t)grow * n + bj * BN;
            #pragma unroll
            for (int nt = 0; nt < 8; nt++) {
                int c0 = wn * 64 + nt * 8 + 2 * q4;
                float2 v;
                v.x = gauss_elem(acc[mt][nt][rr * 2 + 0], sqj[c0],     nsqi, invl);
                v.y = gauss_elem(acc[mt][nt][rr * 2 + 1], sqj[c0 + 1], nsqi, invl);
                *reinterpret_cast<float2*>(orow + c0) = v;
            }
        }
    }
}

// ------------------------------ launch ---------------------------------------
extern "C" void kernel_launch(void* const* d_in, const int* in_sizes, int n_in,
                              void* d_out, int out_size) {
    const float* X = (const float*)d_in[0];
    int n = in_sizes[0] / DDIM;          // 8192
    float* out = (float*)d_out;

    cudaFuncSetAttribute(gk_main, cudaFuncAttributeMaxDynamicSharedMemorySize,
                         SMEM_BYTES);

    gk_sq<<<n / 8, 256>>>(X);            // 1024 CTAs, one warp per row
    gk_colpart<<<64, 1024>>>(X);
    gk_finish<<<1, 1024>>>(n);
    dim3 grid(n / BN, n / BM);
    gk_main<<<grid, 256, SMEM_BYTES>>>(X, out, n);
}